// round 15
// baseline (speedup 1.0000x reference)
#include <cuda_runtime.h>
#include <cuda_bf16.h>
#include <math.h>
#include <stdint.h>

// Problem constants
#define BATCH 2
#define SEQ   2048
#define DIM   4096
#define NHEAD 32
#define HDIM  128
#define MROWS (BATCH * SEQ)   // 4096
#define NELEM (MROWS * DIM)   // 16777216

// pre-split bf16 scratch
__device__ __nv_bfloat16 g_xh[NELEM],  g_xl[NELEM];
__device__ __nv_bfloat16 g_wqh[NELEM], g_wql[NELEM];
__device__ __nv_bfloat16 g_wkh[NELEM], g_wkl[NELEM];
__device__ __nv_bfloat16 g_wvh[NELEM], g_wvl[NELEM];
__device__ __nv_bfloat16 g_woh[NELEM], g_wol[NELEM];
__device__ __nv_bfloat16 g_qh[NELEM],  g_ql[NELEM];
__device__ __nv_bfloat16 g_kh[NELEM],  g_kl[NELEM];
__device__ __nv_bfloat16 g_vh[NELEM],  g_vl[NELEM];
__device__ __nv_bfloat16 g_ah[NELEM],  g_al[NELEM];

// ---------------------------------------------------------------------------
// Helpers
// ---------------------------------------------------------------------------
__device__ __forceinline__ uint32_t smem_u32(const void* p) {
    uint32_t a;
    asm("{ .reg .u64 t; cvta.to.shared.u64 t, %1; cvt.u32.u64 %0, t; }"
        : "=r"(a) : "l"(p));
    return a;
}

__device__ __forceinline__ void cpa16(uint32_t dst, const void* src) {
    asm volatile("cp.async.cg.shared.global [%0], [%1], 16;"
                 :: "r"(dst), "l"(src));
}
#define CP_COMMIT() asm volatile("cp.async.commit_group;" ::: "memory")
#define CP_WAIT(n)  asm volatile("cp.async.wait_group " #n ";" ::: "memory")

__device__ __forceinline__ void ldsm4(uint32_t addr, uint32_t& r0, uint32_t& r1,
                                      uint32_t& r2, uint32_t& r3) {
    asm volatile("ldmatrix.sync.aligned.m8n8.x4.shared.b16 {%0,%1,%2,%3}, [%4];"
                 : "=r"(r0), "=r"(r1), "=r"(r2), "=r"(r3) : "r"(addr));
}
__device__ __forceinline__ void ldsm4t(uint32_t addr, uint32_t& r0, uint32_t& r1,
                                       uint32_t& r2, uint32_t& r3) {
    asm volatile("ldmatrix.sync.aligned.m8n8.x4.trans.shared.b16 {%0,%1,%2,%3}, [%4];"
                 : "=r"(r0), "=r"(r1), "=r"(r2), "=r"(r3) : "r"(addr));
}

__device__ __forceinline__ void mma_bf16(float* c, const uint32_t* a,
                                         const uint32_t* b) {
    asm volatile(
        "mma.sync.aligned.m16n8k16.row.col.f32.bf16.bf16.f32 "
        "{%0,%1,%2,%3}, {%4,%5,%6,%7}, {%8,%9}, {%0,%1,%2,%3};"
        : "+f"(c[0]), "+f"(c[1]), "+f"(c[2]), "+f"(c[3])
        : "r"(a[0]), "r"(a[1]), "r"(a[2]), "r"(a[3]), "r"(b[0]), "r"(b[1]));
}
__device__ __forceinline__ void mma_bf16_2(float* c, const uint32_t* a,
                                           uint32_t b0, uint32_t b1) {
    asm volatile(
        "mma.sync.aligned.m16n8k16.row.col.f32.bf16.bf16.f32 "
        "{%0,%1,%2,%3}, {%4,%5,%6,%7}, {%8,%9}, {%0,%1,%2,%3};"
        : "+f"(c[0]), "+f"(c[1]), "+f"(c[2]), "+f"(c[3])
        : "r"(a[0]), "r"(a[1]), "r"(a[2]), "r"(a[3]), "r"(b0), "r"(b1));
}

__device__ __forceinline__ uint32_t packbf(__nv_bfloat16 a, __nv_bfloat16 b) {
    return ((uint32_t)__bfloat16_as_ushort(b) << 16) | __bfloat16_as_ushort(a);
}
__device__ __forceinline__ void split2(float x, float y, uint32_t& hi, uint32_t& lo) {
    __nv_bfloat16 hx = __float2bfloat16(x);
    __nv_bfloat16 hy = __float2bfloat16(y);
    hi = packbf(hx, hy);
    lo = packbf(__float2bfloat16(x - __bfloat162float(hx)),
                __float2bfloat16(y - __bfloat162float(hy)));
}

// ---------------------------------------------------------------------------
// Merged split kernel
// ---------------------------------------------------------------------------
__global__ __launch_bounds__(512) void split5_kernel(
    const float* __restrict__ s0, const float* __restrict__ s1,
    const float* __restrict__ s2, const float* __restrict__ s3,
    const float* __restrict__ s4) {
    int i = blockIdx.x * blockDim.x + threadIdx.x;
    const float* src;
    __nv_bfloat16 *dh, *dl;
    switch (blockIdx.y) {
        case 0:  src = s0; dh = g_xh;  dl = g_xl;  break;
        case 1:  src = s1; dh = g_wqh; dl = g_wql; break;
        case 2:  src = s2; dh = g_wkh; dl = g_wkl; break;
        case 3:  src = s3; dh = g_wvh; dl = g_wvl; break;
        default: src = s4; dh = g_woh; dl = g_wol; break;
    }
    float4 v = ((const float4*)src)[i];
    uint32_t h0, l0, h1, l1;
    split2(v.x, v.y, h0, l0);
    split2(v.z, v.w, h1, l1);
    ((uint2*)dh)[i] = make_uint2(h0, h1);
    ((uint2*)dl)[i] = make_uint2(l0, l1);
}

// ---------------------------------------------------------------------------
// bf16x3 GEMM core v5: 128x128 tile, BK=32, 512 threads / 16 warps (4x4,
// warp tile 32x32). 5-stage cp.async ring, TWO chunks per wait+sync.
// ---------------------------------------------------------------------------
#define BM 128
#define BN 128
#define BK 32
#define NKC (DIM / BK)   // 128 (even)
#define PITCHB 80

#define OFF_AHI 0
#define OFF_ALO 10240
#define OFF_BHI 20480
#define OFF_BLO 30720
#define STAGE_BYTES 40960
#define NSTG 5
#define GEMM_SMEM (NSTG * STAGE_BYTES)   // 204800
#define GTHREADS 512

#define ISSUE(kc, stg)                                                        \
    {                                                                         \
        uint32_t sb = sbase + (uint32_t)(stg) * STAGE_BYTES;                  \
        size_t gk = (size_t)(kc) * 64;                                        \
        int row = tid >> 2;                                                   \
        int off = (tid & 3) * 16;                                             \
        uint32_t so = (uint32_t)row * PITCHB + off;                           \
        size_t go = (size_t)row * (DIM * 2) + gk + off;                       \
        cpa16(sb + OFF_AHI + so, Ahb + go);                                   \
        cpa16(sb + OFF_ALO + so, Alb + go);                                   \
        cpa16(sb + OFF_BHI + so, Bhb + go);                                   \
        cpa16(sb + OFF_BLO + so, Blb + go);                                   \
        CP_COMMIT();                                                          \
    }

// Invariants (iteration kc, even):
//  - groups 0..kc+2 committed before the wait; wait_group(1) => stages kc,
//    kc+1 resident in ring slots kc%5, (kc+1)%5.
//  - top __syncthreads: all warps finished chunks kc-2, kc-1 (computed last
//    iteration) => ring slots (kc+3)%5, (kc+4)%5 are dead and reusable.
//  - tail: dummy commit_group keeps "leave 1 outstanding" pointing at a
//    group we never read.
#define GEMM_MAINLOOP(Ahb, Alb, Bhb, Blb)                                     \
    const uint32_t lm_off = (uint32_t)(lane & 15) * PITCHB + (lane >> 4) * 16;\
    const uint32_t aAdr0 = (uint32_t)(wm * 32) * PITCHB + lm_off;             \
    const uint32_t bAdr0 = (uint32_t)(wn * 32) * PITCHB + lm_off;             \
    ISSUE(0, 0); ISSUE(1, 1); ISSUE(2, 2);                                    \
    for (int kc = 0; kc < NKC; kc += 2) {                                     \
        CP_WAIT(1);                                                           \
        __syncthreads();                                                      \
        if (kc + 3 < NKC) { ISSUE(kc + 3, (kc + 3) % 5); }                    \
        else { CP_COMMIT(); }                                                 \
        if (kc + 4 < NKC) { ISSUE(kc + 4, (kc + 4) % 5); }                    \
        else { CP_COMMIT(); }                                                 \
        _Pragma("unroll")                                                     \
        for (int half = 0; half < 2; half++) {                                \
            const uint32_t stg = sbase +                                      \
                (uint32_t)((kc + half) % 5) * STAGE_BYTES;                    \
            const uint32_t aHi = stg + OFF_AHI + aAdr0;                       \
            const uint32_t aLo = stg + OFF_ALO + aAdr0;                       \
            const uint32_t bHi = stg + OFF_BHI + bAdr0;                       \
            const uint32_t bLo = stg + OFF_BLO + bAdr0;                       \
            _Pragma("unroll")                                                 \
            for (int s = 0; s < 2; s++) {                                     \
                uint32_t aF[2][4], bH[4][2], bL[4][2];                        \
                _Pragma("unroll")                                             \
                for (int mi = 0; mi < 2; mi++)                                \
                    ldsm4(aHi + mi * (16 * PITCHB) + s * 32,                  \
                          aF[mi][0], aF[mi][1], aF[mi][2], aF[mi][3]);        \
                _Pragma("unroll")                                             \
                for (int nj = 0; nj < 2; nj++) {                              \
                    uint32_t r0, r1, r2, r3;                                  \
                    ldsm4(bHi + nj * (16 * PITCHB) + s * 32, r0, r1, r2, r3); \
                    bH[nj * 2][0] = r0; bH[nj * 2 + 1][0] = r1;               \
                    bH[nj * 2][1] = r2; bH[nj * 2 + 1][1] = r3;               \
                    ldsm4(bLo + nj * (16 * PITCHB) + s * 32, r0, r1, r2, r3); \
                    bL[nj * 2][0] = r0; bL[nj * 2 + 1][0] = r1;               \
                    bL[nj * 2][1] = r2; bL[nj * 2 + 1][1] = r3;               \
                }                                                             \
                _Pragma("unroll")                                             \
                for (int mi = 0; mi < 2; mi++)                                \
                    _Pragma("unroll")                                         \
                    for (int nf = 0; nf < 4; nf++)                            \
                        mma_bf16(acc[mi][nf], aF[mi], bH[nf]);                \
                _Pragma("unroll")                                             \
                for (int mi = 0; mi < 2; mi++)                                \
                    _Pragma("unroll")                                         \
                    for (int nf = 0; nf < 4; nf++)                            \
                        mma_bf16(acc[mi][nf], aF[mi], bL[nf]);                \
                _Pragma("unroll")                                             \
                for (int mi = 0; mi < 2; mi++)                                \
                    ldsm4(aLo + mi * (16 * PITCHB) + s * 32,                  \
                          aF[mi][0], aF[mi][1], aF[mi][2], aF[mi][3]);        \
                _Pragma("unroll")                                             \
                for (int mi = 0; mi < 2; mi++)                                \
                    _Pragma("unroll")                                         \
                    for (int nf = 0; nf < 4; nf++)                            \
                        mma_bf16(acc[mi][nf], aF[mi], bH[nf]);                \
            }                                                                 \
        }                                                                     \
    }

// ---------------------------------------------------------------------------
// QKV GEMM, merged via grid.z in {0=Q,1=K,2=V}. RoPE+scale fused in epilogue
// with smem-staged trig. Output stored pre-split bf16 hi/lo.
// ---------------------------------------------------------------------------
#define TRIG_PITCH 66

__global__ __launch_bounds__(GTHREADS, 1)
void gemm_qkv(const __nv_bfloat16* __restrict__ Xh,
              const __nv_bfloat16* __restrict__ Xl,
              const float* __restrict__ fcos, const float* __restrict__ fsin) {
    extern __shared__ char smem_raw[];
    const uint32_t sbase = smem_u32(smem_raw);
    const int tid  = threadIdx.x;
    const int wid  = tid >> 5;
    const int lane = tid & 31;
    const int wm   = wid >> 2;        // 0..3
    const int wn   = wid & 3;         // 0..3
    const int m0   = blockIdx.y * BM;
    const int n0   = blockIdx.x * BN;
    const int z    = blockIdx.z;

    const __nv_bfloat16 *Wh, *Wl;
    __nv_bfloat16 *OH, *OL;
    if (z == 0)      { Wh = g_wqh; Wl = g_wql; OH = g_qh; OL = g_ql; }
    else if (z == 1) { Wh = g_wkh; Wl = g_wkl; OH = g_kh; OL = g_kl; }
    else             { Wh = g_wvh; Wl = g_wvl; OH = g_vh; OL = g_vl; }

    const char* Ahb = (const char*)(Xh + (size_t)m0 * DIM);
    const char* Alb = (const char*)(Xl + (size_t)m0 * DIM);
    const char* Bhb = (const char*)(Wh + (size_t)n0 * DIM);
    const char* Blb = (const char*)(Wl + (size_t)n0 * DIM);

    float acc[2][4][4];
#pragma unroll
    for (int i = 0; i < 2; i++)
#pragma unroll
        for (int j = 0; j < 4; j++)
#pragma unroll
            for (int k = 0; k < 4; k++) acc[i][j][k] = 0.0f;

    GEMM_MAINLOOP(Ahb, Alb, Bhb, Blb)

    // Stage trig table into dead pipeline smem
    __syncthreads();
    float2* trig = (float2*)smem_raw;
    if (z < 2) {
        for (int i = tid; i < 128 * 64; i += GTHREADS) {
            int sl = i >> 6, j = i & 63;
            int s = (m0 + sl) & (SEQ - 1);
            trig[sl * TRIG_PITCH + j] = make_float2(fcos[s * 64 + j],
                                                    fsin[s * 64 + j]);
        }
        __syncthreads();
    }

    const float qscale = 0.08838834764831845f;
#pragma unroll
    for (int mi = 0; mi < 2; mi++) {
#pragma unroll
        for (int nf = 0; nf < 4; nf++) {
            int rl  = wm * 32 + mi * 16 + (lane >> 2);
            int row = m0 + rl;
            int col = n0 + wn * 32 + nf * 8 + (lane & 3) * 2;
            float c0 = acc[mi][nf][0], c1 = acc[mi][nf][1];
            float c2 = acc[mi][nf][2], c3 = acc[mi][nf][3];
            if (z < 2) {
                int j = (wn * 32 + nf * 8) / 2 + (lane & 3);
                float2 tA = trig[rl * TRIG_PITCH + j];
                float2 tB = trig[(rl + 8) * TRIG_PITCH + j];
                float r0 = c0 * tA.x - c1 * tA.y, i0 = c0 * tA.y + c1 * tA.x;
                float r1 = c2 * tB.x - c3 * tB.y, i1 = c2 * tB.y + c3 * tB.x;
                if (z == 0) { r0 *= qscale; i0 *= qscale; r1 *= qscale; i1 *= qscale; }
                c0 = r0; c1 = i0; c2 = r1; c3 = i1;
            }
            uint32_t hi, lo;
            split2(c0, c1, hi, lo);
            *(uint32_t*)&OH[(size_t)row * DIM + col] = hi;
            *(uint32_t*)&OL[(size_t)row * DIM + col] = lo;
            split2(c2, c3, hi, lo);
            *(uint32_t*)&OH[(size_t)(row + 8) * DIM + col] = hi;
            *(uint32_t*)&OL[(size_t)(row + 8) * DIM + col] = lo;
        }
    }
}

// ---------------------------------------------------------------------------
// O-projection GEMM
// ---------------------------------------------------------------------------
__global__ __launch_bounds__(GTHREADS, 1)
void gemm_o(const __nv_bfloat16* __restrict__ Ah,
            const __nv_bfloat16* __restrict__ Al,
            const __nv_bfloat16* __restrict__ Bh,
            const __nv_bfloat16* __restrict__ Bl,
            float* __restrict__ C) {
    extern __shared__ char smem_raw[];
    const uint32_t sbase = smem_u32(smem_raw);
    const int tid  = threadIdx.x;
    const int wid  = tid >> 5;
    const int lane = tid & 31;
    const int wm   = wid >> 2;
    const int wn   = wid & 3;
    const int m0   = blockIdx.y * BM;
    const int n0   = blockIdx.x * BN;

    const char* Ahb = (const char*)(Ah + (size_t)m0 * DIM);
    const char* Alb = (const char*)(Al + (size_t)m0 * DIM);
    const char* Bhb = (const char*)(Bh + (size_t)n0 * DIM);
    const char* Blb = (const char*)(Bl + (size_t)n0 * DIM);

    float acc[2][4][4];
#pragma unroll
    for (int i = 0; i < 2; i++)
#pragma unroll
        for (int j = 0; j < 4; j++)
#pragma unroll
            for (int k = 0; k < 4; k++) acc[i][j][k] = 0.0f;

    GEMM_MAINLOOP(Ahb, Alb, Bhb, Blb)

#pragma unroll
    for (int mi = 0; mi < 2; mi++) {
#pragma unroll
        for (int nf = 0; nf < 4; nf++) {
            int row = m0 + wm * 32 + mi * 16 + (lane >> 2);
            int col = n0 + wn * 32 + nf * 8 + (lane & 3) * 2;
            *(float2*)&C[(size_t)row * DIM + col] =
                make_float2(acc[mi][nf][0], acc[mi][nf][1]);
            *(float2*)&C[(size_t)(row + 8) * DIM + col] =
                make_float2(acc[mi][nf][2], acc[mi][nf][3]);
        }
    }
}

// ---------------------------------------------------------------------------
// Flash attention (R5 exactly — at the half-rate HMMA ceiling; unchanged)
// ---------------------------------------------------------------------------
#define FPITCH 272
#define FQH 0
#define FQL (128 * FPITCH)
#define FSTG0 (2 * 128 * FPITCH)
#define FKH 0
#define FKL (64 * FPITCH)
#define FVH (128 * FPITCH)
#define FVL (192 * FPITCH)
#define FSTAGE (256 * FPITCH)
#define FLASH_SMEM (FSTG0 + 2 * FSTAGE)

__global__ __launch_bounds__(256)
void flash_mma() {
    extern __shared__ char smem_raw[];
    const uint32_t sbase = smem_u32(smem_raw);
    const int tid  = threadIdx.x;
    const int w    = tid >> 5;
    const int lane = tid & 31;
    const int qt = blockIdx.x;
    const int h  = blockIdx.y;
    const int b  = blockIdx.z;
    const int q0 = qt * 128;
    const size_t hoff = (size_t)h * HDIM;

    const char* khb = (const char*)g_kh;
    const char* klb = (const char*)g_kl;
    const char* vhb = (const char*)g_vh;
    const char* vlb = (const char*)g_vl;

    {
        const char* qhb = (const char*)g_qh;
        const char* qlb = (const char*)g_ql;
        for (int i = tid; i < 2048; i += 256) {
            int r = i >> 4, sg = (i & 15) * 16;
            size_t go = ((size_t)(b * SEQ + q0 + r) * DIM + hoff) * 2 + sg;
            uint32_t so = (uint32_t)r * FPITCH + sg;
            *(uint4*)(smem_raw + FQH + so) = *(const uint4*)(qhb + go);
            *(uint4*)(smem_raw + FQL + so) = *(const uint4*)(qlb + go);
        }
    }

#define LOADKV(t, stg)                                                        \
    {                                                                         \
        uint32_t sp = sbase + FSTG0 + (uint32_t)(stg) * FSTAGE;               \
        const int j0 = (t) * 64;                                              \
        _Pragma("unroll")                                                     \
        for (int u = 0; u < 4; u++) {                                         \
            int seg = tid + u * 256;                                          \
            int row = seg >> 4;                                               \
            int off = (seg & 15) * 16;                                        \
            uint32_t so = (uint32_t)row * FPITCH + off;                       \
            size_t go = ((size_t)(b * SEQ + j0 + row) * DIM + hoff) * 2 + off;\
            cpa16(sp + FKH + so, khb + go);                                   \
            cpa16(sp + FKL + so, klb + go);                                   \
            cpa16(sp + FVH + so, vhb + go);                                   \
            cpa16(sp + FVL + so, vlb + go);                                   \
        }                                                                     \
        CP_COMMIT();                                                          \
    }

    LOADKV(0, 0);

    float o[16][4];
#pragma unroll
    for (int nf = 0; nf < 16; nf++)
#pragma unroll
        for (int k = 0; k < 4; k++) o[nf][k] = 0.0f;
    float m0 = -INFINITY, m1 = -INFINITY, l0s = 0.0f, l1s = 0.0f;

    const uint32_t lmA = (uint32_t)(lane & 15) * FPITCH + (lane >> 4) * 16;
    const uint32_t qAdr = sbase + (uint32_t)(w * 16) * FPITCH + lmA;
    const uint32_t lmV = (uint32_t)(((lane >> 3) & 1) * 8 + (lane & 7)) * FPITCH
                         + (lane >> 4) * 16;

    for (int t = 0; t < 32; t++) {
        const int cur = t & 1;
        CP_WAIT(0);
        __syncthreads();
        if (t + 1 < 32) { LOADKV(t + 1, 1 - cur); }

        const uint32_t stg = sbase + FSTG0 + (uint32_t)cur * FSTAGE;

        float sc[8][4];
#pragma unroll
        for (int nf = 0; nf < 8; nf++)
#pragma unroll
            for (int k = 0; k < 4; k++) sc[nf][k] = 0.0f;

#pragma unroll
        for (int ks = 0; ks < 8; ks++) {
            uint32_t qh[4], ql[4];
            ldsm4(qAdr + FQH + ks * 32, qh[0], qh[1], qh[2], qh[3]);
            ldsm4(qAdr + FQL + ks * 32, ql[0], ql[1], ql[2], ql[3]);
#pragma unroll
            for (int nfp = 0; nfp < 4; nfp++) {
                uint32_t kAdr = stg + (uint32_t)(nfp * 16) * FPITCH + lmA + ks * 32;
                uint32_t kh0, kh1, kh2, kh3, kl0, kl1, kl2, kl3;
                ldsm4(kAdr + FKH, kh0, kh1, kh2, kh3);
                ldsm4(kAdr + FKL, kl0, kl1, kl2, kl3);
                mma_bf16_2(sc[nfp * 2],     qh, kh0, kh2);
                mma_bf16_2(sc[nfp * 2 + 1], qh, kh1, kh3);
                mma_bf16_2(sc[nfp * 2],     qh, kl0, kl2);
                mma_bf16_2(sc[nfp * 2 + 1], qh, kl1, kl3);
                mma_bf16_2(sc[nfp * 2],     ql, kh0, kh2);
                mma_bf16_2(sc[nfp * 2 + 1], ql, kh1, kh3);
            }
        }

        float mx0 = -INFINITY, mx1 = -INFINITY;
#pragma unroll
        for (int nf = 0; nf < 8; nf++) {
            mx0 = fmaxf(mx0, fmaxf(sc[nf][0], sc[nf][1]));
            mx1 = fmaxf(mx1, fmaxf(sc[nf][2], sc[nf][3]));
        }
        mx0 = fmaxf(mx0, __shfl_xor_sync(0xffffffffu, mx0, 1));
        mx0 = fmaxf(mx0, __shfl_xor_sync(0xffffffffu, mx0, 2));
        mx1 = fmaxf(mx1, __shfl_xor_sync(0xffffffffu, mx1, 1));
        mx1 = fmaxf(mx1, __shfl_xor_sync(0xffffffffu, mx1, 2));

        float mn0 = fmaxf(m0, mx0), mn1 = fmaxf(m1, mx1);
        float a0 = __expf(m0 - mn0), a1 = __expf(m1 - mn1);
        float rs0 = 0.0f, rs1 = 0.0f;
#pragma unroll
        for (int nf = 0; nf < 8; nf++) {
            sc[nf][0] = __expf(sc[nf][0] - mn0);
            sc[nf][1] = __expf(sc[nf][1] - mn0);
            sc[nf][2] = __expf(sc[nf][2] - mn1);
            sc[nf][3] = __expf(sc[nf][3] - mn1);
            rs0 += sc[nf][0] + sc[nf][1];
            rs1 += sc[nf][2] + sc[nf][3];
        }
        rs0 += __shfl_xor_sync(0xffffffffu, rs0, 1);
        rs0 += __shfl_xor_sync(0xffffffffu, rs0, 2);
        rs1 += __shfl_xor_sync(0xffffffffu, rs1, 1);
        rs1 += __shfl_xor_sync(0xffffffffu, rs1, 2);
        l0s = l0s * a0 + rs0;
        l1s = l1s * a1 + rs1;
        m0 = mn0; m1 = mn1;
#pragma unroll
        for (int nf = 0; nf < 16; nf++) {
            o[nf][0] *= a0; o[nf][1] *= a0;
            o[nf][2] *= a1; o[nf][3] *= a1;
        }

        uint32_t ph[4][4], pl[4][4];
#pragma unroll
        for (int ks = 0; ks < 4; ks++) {
            split2(sc[2 * ks][0],     sc[2 * ks][1],     ph[ks][0], pl[ks][0]);
            split2(sc[2 * ks][2],     sc[2 * ks][3],     ph[ks][1], pl[ks][1]);
            split2(sc[2 * ks + 1][0], sc[2 * ks + 1][1], ph[ks][2], pl[ks][2]);
            split2(sc[2 * ks + 1][2], sc[2 * ks + 1][3], ph[ks][3], pl[ks][3]);
        }

#pragma unroll
        for (int nfp = 0; nfp < 8; nfp++) {
#pragma unroll
            for (int ks = 0; ks < 4; ks++) {
                uint32_t vAdr = stg + (uint32_t)(ks * 16) * FPITCH + lmV + nfp * 32;
                uint32_t vh0, vh1, vh2, vh3, vl0, vl1, vl2, vl3;
                ldsm4t(vAdr + FVH, vh0, vh1, vh2, vh3);
                ldsm4t(vAdr + FVL, vl0, vl1, vl2, vl3);
                mma_bf16_2(o[nfp * 2],     ph[ks], vh0, vh1);
                mma_bf16_2(o[nfp * 2 + 1], ph[ks], vh2, vh3);
                mma_bf16_2(o[nfp * 2],     ph[ks], vl0, vl1);
                mma_bf16_2(o[nfp * 2 + 1], ph[ks], vl2, vl3);
                mma_bf16_2(o[nfp * 2],     pl[ks], vh0, vh1);
                mma_bf16_2(o[nfp * 2 + 1], pl[ks], vh2, vh3);
            }
        }
        __syncthreads();
    }

    const float inv0 = 1.0f / l0s;
    const float inv1 = 1.0f / l1s;
    const int g = lane >> 2;
    const int tq = lane & 3;
    const int row0 = q0 + w * 16 + g;
    size_t base0 = ((size_t)(b * SEQ + row0)) * DIM + hoff + tq * 2;
    size_t base1 = base0 + (size_t)8 * DIM;
#pragma unroll
    for (int nf = 0; nf < 16; nf++) {
        uint32_t hi, lo;
        split2(o[nf][0] * inv0, o[nf][1] * inv0, hi, lo);
        *(uint32_t*)&g_ah[base0 + nf * 8] = hi;
        *(uint32_t*)&g_al[base0 + nf * 8] = lo;
        split2(o[nf][2] * inv1, o[nf][3] * inv1, hi, lo);
        *(uint32_t*)&g_ah[base1 + nf * 8] = hi;
        *(uint32_t*)&g_al[base1 + nf * 8] = lo;
    }
#undef LOADKV
}

// ---------------------------------------------------------------------------
// Launch
// ---------------------------------------------------------------------------
extern "C" void kernel_launch(void* const* d_in, const int* in_sizes, int n_in,
                              void* d_out, int out_size) {
    const float* x    = (const float*)d_in[0];
    const float* wq   = (const float*)d_in[1];
    const float* wk   = (const float*)d_in[2];
    const float* wv   = (const float*)d_in[3];
    const float* wo   = (const float*)d_in[4];
    const float* fcos = (const float*)d_in[5];
    const float* fsin = (const float*)d_in[6];
    float* out = (float*)d_out;

    __nv_bfloat16 *xh, *xl, *woh, *wol, *ah, *al;
    cudaGetSymbolAddress((void**)&xh,  g_xh);
    cudaGetSymbolAddress((void**)&xl,  g_xl);
    cudaGetSymbolAddress((void**)&woh, g_woh);
    cudaGetSymbolAddress((void**)&wol, g_wol);
    cudaGetSymbolAddress((void**)&ah,  g_ah);
    cudaGetSymbolAddress((void**)&al,  g_al);

    cudaFuncSetAttribute(gemm_qkv, cudaFuncAttributeMaxDynamicSharedMemorySize,
                         GEMM_SMEM);
    cudaFuncSetAttribute(gemm_o, cudaFuncAttributeMaxDynamicSharedMemorySize,
                         GEMM_SMEM);
    cudaFuncSetAttribute(flash_mma, cudaFuncAttributeMaxDynamicSharedMemorySize,
                         FLASH_SMEM);

    split5_kernel<<<dim3(NELEM / 4 / 512, 5), 512>>>(x, wq, wk, wv, wo);

    gemm_qkv<<<dim3(DIM / BN, MROWS / BM, 3), GTHREADS, GEMM_SMEM>>>(xh, xl,
                                                                     fcos, fsin);

    flash_mma<<<dim3(SEQ / 128, NHEAD, BATCH), 256, FLASH_SMEM>>>();

    gemm_o<<<dim3(DIM / BN, MROWS / BM), GTHREADS, GEMM_SMEM>>>(ah, al, woh,
                                                                wol, out);
}

// round 16
// speedup vs baseline: 1.0256x; 1.0256x over previous
#include <cuda_runtime.h>
#include <cuda_bf16.h>
#include <math.h>
#include <stdint.h>

// Problem constants
#define BATCH 2
#define SEQ   2048
#define DIM   4096
#define NHEAD 32
#define HDIM  128
#define MROWS (BATCH * SEQ)   // 4096
#define NELEM (MROWS * DIM)   // 16777216

// pre-split bf16 scratch
__device__ __nv_bfloat16 g_xh[NELEM],  g_xl[NELEM];
__device__ __nv_bfloat16 g_wqh[NELEM], g_wql[NELEM];
__device__ __nv_bfloat16 g_wkh[NELEM], g_wkl[NELEM];
__device__ __nv_bfloat16 g_wvh[NELEM], g_wvl[NELEM];
__device__ __nv_bfloat16 g_woh[NELEM], g_wol[NELEM];
__device__ __nv_bfloat16 g_qh[NELEM],  g_ql[NELEM];
__device__ __nv_bfloat16 g_kh[NELEM],  g_kl[NELEM];
__device__ __nv_bfloat16 g_vh[NELEM],  g_vl[NELEM];
__device__ __nv_bfloat16 g_ah[NELEM],  g_al[NELEM];

// ---------------------------------------------------------------------------
// Helpers
// ---------------------------------------------------------------------------
__device__ __forceinline__ uint32_t smem_u32(const void* p) {
    uint32_t a;
    asm("{ .reg .u64 t; cvta.to.shared.u64 t, %1; cvt.u32.u64 %0, t; }"
        : "=r"(a) : "l"(p));
    return a;
}

__device__ __forceinline__ void cpa16(uint32_t dst, const void* src) {
    asm volatile("cp.async.cg.shared.global [%0], [%1], 16;"
                 :: "r"(dst), "l"(src));
}
#define CP_COMMIT() asm volatile("cp.async.commit_group;" ::: "memory")
#define CP_WAIT(n)  asm volatile("cp.async.wait_group " #n ";" ::: "memory")

__device__ __forceinline__ void ldsm4(uint32_t addr, uint32_t& r0, uint32_t& r1,
                                      uint32_t& r2, uint32_t& r3) {
    asm volatile("ldmatrix.sync.aligned.m8n8.x4.shared.b16 {%0,%1,%2,%3}, [%4];"
                 : "=r"(r0), "=r"(r1), "=r"(r2), "=r"(r3) : "r"(addr));
}
__device__ __forceinline__ void ldsm4t(uint32_t addr, uint32_t& r0, uint32_t& r1,
                                       uint32_t& r2, uint32_t& r3) {
    asm volatile("ldmatrix.sync.aligned.m8n8.x4.trans.shared.b16 {%0,%1,%2,%3}, [%4];"
                 : "=r"(r0), "=r"(r1), "=r"(r2), "=r"(r3) : "r"(addr));
}

__device__ __forceinline__ void mma_bf16(float* c, const uint32_t* a,
                                         const uint32_t* b) {
    asm volatile(
        "mma.sync.aligned.m16n8k16.row.col.f32.bf16.bf16.f32 "
        "{%0,%1,%2,%3}, {%4,%5,%6,%7}, {%8,%9}, {%0,%1,%2,%3};"
        : "+f"(c[0]), "+f"(c[1]), "+f"(c[2]), "+f"(c[3])
        : "r"(a[0]), "r"(a[1]), "r"(a[2]), "r"(a[3]), "r"(b[0]), "r"(b[1]));
}
__device__ __forceinline__ void mma_bf16_2(float* c, const uint32_t* a,
                                           uint32_t b0, uint32_t b1) {
    asm volatile(
        "mma.sync.aligned.m16n8k16.row.col.f32.bf16.bf16.f32 "
        "{%0,%1,%2,%3}, {%4,%5,%6,%7}, {%8,%9}, {%0,%1,%2,%3};"
        : "+f"(c[0]), "+f"(c[1]), "+f"(c[2]), "+f"(c[3])
        : "r"(a[0]), "r"(a[1]), "r"(a[2]), "r"(a[3]), "r"(b0), "r"(b1));
}

__device__ __forceinline__ uint32_t packbf(__nv_bfloat16 a, __nv_bfloat16 b) {
    return ((uint32_t)__bfloat16_as_ushort(b) << 16) | __bfloat16_as_ushort(a);
}
__device__ __forceinline__ void split2(float x, float y, uint32_t& hi, uint32_t& lo) {
    __nv_bfloat16 hx = __float2bfloat16(x);
    __nv_bfloat16 hy = __float2bfloat16(y);
    hi = packbf(hx, hy);
    lo = packbf(__float2bfloat16(x - __bfloat162float(hx)),
                __float2bfloat16(y - __bfloat162float(hy)));
}

// ---------------------------------------------------------------------------
// Merged split kernel
// ---------------------------------------------------------------------------
__global__ __launch_bounds__(256) void split5_kernel(
    const float* __restrict__ s0, const float* __restrict__ s1,
    const float* __restrict__ s2, const float* __restrict__ s3,
    const float* __restrict__ s4) {
    int i = blockIdx.x * blockDim.x + threadIdx.x;
    const float* src;
    __nv_bfloat16 *dh, *dl;
    switch (blockIdx.y) {
        case 0:  src = s0; dh = g_xh;  dl = g_xl;  break;
        case 1:  src = s1; dh = g_wqh; dl = g_wql; break;
        case 2:  src = s2; dh = g_wkh; dl = g_wkl; break;
        case 3:  src = s3; dh = g_wvh; dl = g_wvl; break;
        default: src = s4; dh = g_woh; dl = g_wol; break;
    }
    float4 v = ((const float4*)src)[i];
    uint32_t h0, l0, h1, l1;
    split2(v.x, v.y, h0, l0);
    split2(v.z, v.w, h1, l1);
    ((uint2*)dh)[i] = make_uint2(h0, h1);
    ((uint2*)dl)[i] = make_uint2(l0, l1);
}

// ---------------------------------------------------------------------------
// bf16x3 GEMM core (R11): 128x128 tile, BK=32, 512 threads / 16 warps (4x4,
// warp tile 32x32) -> 4 warps per SMSP. 4-stage cp.async pipeline.
// ---------------------------------------------------------------------------
#define BM 128
#define BN 128
#define BK 32
#define NKC (DIM / BK)   // 128
#define PITCHB 80

#define OFF_AHI 0
#define OFF_ALO 10240
#define OFF_BHI 20480
#define OFF_BLO 30720
#define STAGE_BYTES 40960
#define GEMM_SMEM (4 * STAGE_BYTES)   // 163840
#define GTHREADS 512

#define ISSUE(kc, stg)                                                        \
    {                                                                         \
        uint32_t sb = sbase + (uint32_t)(stg) * STAGE_BYTES;                  \
        size_t gk = (size_t)(kc) * 64;                                        \
        int row = tid >> 2;                                                   \
        int off = (tid & 3) * 16;                                             \
        uint32_t so = (uint32_t)row * PITCHB + off;                           \
        size_t go = (size_t)row * (DIM * 2) + gk + off;                       \
        cpa16(sb + OFF_AHI + so, Ahb + go);                                   \
        cpa16(sb + OFF_ALO + so, Alb + go);                                   \
        cpa16(sb + OFF_BHI + so, Bhb + go);                                   \
        cpa16(sb + OFF_BLO + so, Blb + go);                                   \
        CP_COMMIT();                                                          \
    }

#define GEMM_MAINLOOP(Ahb, Alb, Bhb, Blb)                                     \
    const uint32_t lm_off = (uint32_t)(lane & 15) * PITCHB + (lane >> 4) * 16;\
    const uint32_t aAdr0 = (uint32_t)(wm * 32) * PITCHB + lm_off;             \
    const uint32_t bAdr0 = (uint32_t)(wn * 32) * PITCHB + lm_off;             \
    ISSUE(0, 0); ISSUE(1, 1); ISSUE(2, 2);                                    \
    for (int kc = 0; kc < NKC; kc++) {                                        \
        CP_WAIT(2);                                                           \
        __syncthreads();                                                      \
        if (kc + 3 < NKC) { ISSUE(kc + 3, (kc + 3) & 3); }                    \
        else { CP_COMMIT(); }                                                 \
        const uint32_t stg = sbase + (uint32_t)(kc & 3) * STAGE_BYTES;        \
        const uint32_t aHi = stg + OFF_AHI + aAdr0;                           \
        const uint32_t aLo = stg + OFF_ALO + aAdr0;                           \
        const uint32_t bHi = stg + OFF_BHI + bAdr0;                           \
        const uint32_t bLo = stg + OFF_BLO + bAdr0;                           \
        _Pragma("unroll")                                                     \
        for (int s = 0; s < 2; s++) {                                         \
            uint32_t aF[2][4], bH[4][2], bL[4][2];                            \
            _Pragma("unroll")                                                 \
            for (int mi = 0; mi < 2; mi++)                                    \
                ldsm4(aHi + mi * (16 * PITCHB) + s * 32,                      \
                      aF[mi][0], aF[mi][1], aF[mi][2], aF[mi][3]);            \
            _Pragma("unroll")                                                 \
            for (int nj = 0; nj < 2; nj++) {                                  \
                uint32_t r0, r1, r2, r3;                                      \
                ldsm4(bHi + nj * (16 * PITCHB) + s * 32, r0, r1, r2, r3);     \
                bH[nj * 2][0] = r0; bH[nj * 2 + 1][0] = r1;                   \
                bH[nj * 2][1] = r2; bH[nj * 2 + 1][1] = r3;                   \
                ldsm4(bLo + nj * (16 * PITCHB) + s * 32, r0, r1, r2, r3);     \
                bL[nj * 2][0] = r0; bL[nj * 2 + 1][0] = r1;                   \
                bL[nj * 2][1] = r2; bL[nj * 2 + 1][1] = r3;                   \
            }                                                                 \
            _Pragma("unroll")                                                 \
            for (int mi = 0; mi < 2; mi++)                                    \
                _Pragma("unroll")                                             \
                for (int nf = 0; nf < 4; nf++)                                \
                    mma_bf16(acc[mi][nf], aF[mi], bH[nf]);                    \
            _Pragma("unroll")                                                 \
            for (int mi = 0; mi < 2; mi++)                                    \
                _Pragma("unroll")                                             \
                for (int nf = 0; nf < 4; nf++)                                \
                    mma_bf16(acc[mi][nf], aF[mi], bL[nf]);                    \
            _Pragma("unroll")                                                 \
            for (int mi = 0; mi < 2; mi++)                                    \
                ldsm4(aLo + mi * (16 * PITCHB) + s * 32,                      \
                      aF[mi][0], aF[mi][1], aF[mi][2], aF[mi][3]);            \
            _Pragma("unroll")                                                 \
            for (int mi = 0; mi < 2; mi++)                                    \
                _Pragma("unroll")                                             \
                for (int nf = 0; nf < 4; nf++)                                \
                    mma_bf16(acc[mi][nf], aF[mi], bH[nf]);                    \
        }                                                                     \
        __syncthreads();                                                      \
    }

// ---------------------------------------------------------------------------
// QKV GEMM (one launch per z). RoPE+scale fused with smem-staged trig.
// ---------------------------------------------------------------------------
#define TRIG_PITCH 66

__global__ __launch_bounds__(GTHREADS, 1)
void gemm_qkv(const __nv_bfloat16* __restrict__ Xh,
              const __nv_bfloat16* __restrict__ Xl,
              const __nv_bfloat16* __restrict__ Wh,
              const __nv_bfloat16* __restrict__ Wl,
              __nv_bfloat16* __restrict__ OH,
              __nv_bfloat16* __restrict__ OL,
              const float* __restrict__ fcos, const float* __restrict__ fsin,
              int z) {
    extern __shared__ char smem_raw[];
    const uint32_t sbase = smem_u32(smem_raw);
    const int tid  = threadIdx.x;
    const int wid  = tid >> 5;
    const int lane = tid & 31;
    const int wm   = wid >> 2;        // 0..3
    const int wn   = wid & 3;         // 0..3
    const int m0   = blockIdx.y * BM;
    const int n0   = blockIdx.x * BN;

    const char* Ahb = (const char*)(Xh + (size_t)m0 * DIM);
    const char* Alb = (const char*)(Xl + (size_t)m0 * DIM);
    const char* Bhb = (const char*)(Wh + (size_t)n0 * DIM);
    const char* Blb = (const char*)(Wl + (size_t)n0 * DIM);

    float acc[2][4][4];
#pragma unroll
    for (int i = 0; i < 2; i++)
#pragma unroll
        for (int j = 0; j < 4; j++)
#pragma unroll
            for (int k = 0; k < 4; k++) acc[i][j][k] = 0.0f;

    GEMM_MAINLOOP(Ahb, Alb, Bhb, Blb)

    // Stage trig table into dead pipeline smem
    float2* trig = (float2*)smem_raw;
    if (z < 2) {
        for (int i = tid; i < 128 * 64; i += GTHREADS) {
            int sl = i >> 6, j = i & 63;
            int s = (m0 + sl) & (SEQ - 1);
            trig[sl * TRIG_PITCH + j] = make_float2(fcos[s * 64 + j],
                                                    fsin[s * 64 + j]);
        }
        __syncthreads();
    }

    const float qscale = 0.08838834764831845f;
#pragma unroll
    for (int mi = 0; mi < 2; mi++) {
#pragma unroll
        for (int nf = 0; nf < 4; nf++) {
            int rl  = wm * 32 + mi * 16 + (lane >> 2);
            int row = m0 + rl;
            int col = n0 + wn * 32 + nf * 8 + (lane & 3) * 2;
            float c0 = acc[mi][nf][0], c1 = acc[mi][nf][1];
            float c2 = acc[mi][nf][2], c3 = acc[mi][nf][3];
            if (z < 2) {
                int j = (wn * 32 + nf * 8) / 2 + (lane & 3);
                float2 tA = trig[rl * TRIG_PITCH + j];
                float2 tB = trig[(rl + 8) * TRIG_PITCH + j];
                float r0 = c0 * tA.x - c1 * tA.y, i0 = c0 * tA.y + c1 * tA.x;
                float r1 = c2 * tB.x - c3 * tB.y, i1 = c2 * tB.y + c3 * tB.x;
                if (z == 0) { r0 *= qscale; i0 *= qscale; r1 *= qscale; i1 *= qscale; }
                c0 = r0; c1 = i0; c2 = r1; c3 = i1;
            }
            uint32_t hi, lo;
            split2(c0, c1, hi, lo);
            *(uint32_t*)&OH[(size_t)row * DIM + col] = hi;
            *(uint32_t*)&OL[(size_t)row * DIM + col] = lo;
            split2(c2, c3, hi, lo);
            *(uint32_t*)&OH[(size_t)(row + 8) * DIM + col] = hi;
            *(uint32_t*)&OL[(size_t)(row + 8) * DIM + col] = lo;
        }
    }
}

// ---------------------------------------------------------------------------
// O-projection GEMM (512 threads)
// ---------------------------------------------------------------------------
__global__ __launch_bounds__(GTHREADS, 1)
void gemm_o(const __nv_bfloat16* __restrict__ Ah,
            const __nv_bfloat16* __restrict__ Al,
            const __nv_bfloat16* __restrict__ Bh,
            const __nv_bfloat16* __restrict__ Bl,
            float* __restrict__ C) {
    extern __shared__ char smem_raw[];
    const uint32_t sbase = smem_u32(smem_raw);
    const int tid  = threadIdx.x;
    const int wid  = tid >> 5;
    const int lane = tid & 31;
    const int wm   = wid >> 2;
    const int wn   = wid & 3;
    const int m0   = blockIdx.y * BM;
    const int n0   = blockIdx.x * BN;

    const char* Ahb = (const char*)(Ah + (size_t)m0 * DIM);
    const char* Alb = (const char*)(Al + (size_t)m0 * DIM);
    const char* Bhb = (const char*)(Bh + (size_t)n0 * DIM);
    const char* Blb = (const char*)(Bl + (size_t)n0 * DIM);

    float acc[2][4][4];
#pragma unroll
    for (int i = 0; i < 2; i++)
#pragma unroll
        for (int j = 0; j < 4; j++)
#pragma unroll
            for (int k = 0; k < 4; k++) acc[i][j][k] = 0.0f;

    GEMM_MAINLOOP(Ahb, Alb, Bhb, Blb)

#pragma unroll
    for (int mi = 0; mi < 2; mi++) {
#pragma unroll
        for (int nf = 0; nf < 4; nf++) {
            int row = m0 + wm * 32 + mi * 16 + (lane >> 2);
            int col = n0 + wn * 32 + nf * 8 + (lane & 3) * 2;
            *(float2*)&C[(size_t)row * DIM + col] =
                make_float2(acc[mi][nf][0], acc[mi][nf][1]);
            *(float2*)&C[(size_t)(row + 8) * DIM + col] =
                make_float2(acc[mi][nf][2], acc[mi][nf][3]);
        }
    }
}

// ---------------------------------------------------------------------------
// Flash attention (R5 exactly — at the half-rate HMMA ceiling)
// ---------------------------------------------------------------------------
#define FPITCH 272
#define FQH 0
#define FQL (128 * FPITCH)
#define FSTG0 (2 * 128 * FPITCH)
#define FKH 0
#define FKL (64 * FPITCH)
#define FVH (128 * FPITCH)
#define FVL (192 * FPITCH)
#define FSTAGE (256 * FPITCH)
#define FLASH_SMEM (FSTG0 + 2 * FSTAGE)

__global__ __launch_bounds__(256)
void flash_mma() {
    extern __shared__ char smem_raw[];
    const uint32_t sbase = smem_u32(smem_raw);
    const int tid  = threadIdx.x;
    const int w    = tid >> 5;
    const int lane = tid & 31;
    const int qt = blockIdx.x;
    const int h  = blockIdx.y;
    const int b  = blockIdx.z;
    const int q0 = qt * 128;
    const size_t hoff = (size_t)h * HDIM;

    const char* khb = (const char*)g_kh;
    const char* klb = (const char*)g_kl;
    const char* vhb = (const char*)g_vh;
    const char* vlb = (const char*)g_vl;

    {
        const char* qhb = (const char*)g_qh;
        const char* qlb = (const char*)g_ql;
        for (int i = tid; i < 2048; i += 256) {
            int r = i >> 4, sg = (i & 15) * 16;
            size_t go = ((size_t)(b * SEQ + q0 + r) * DIM + hoff) * 2 + sg;
            uint32_t so = (uint32_t)r * FPITCH + sg;
            *(uint4*)(smem_raw + FQH + so) = *(const uint4*)(qhb + go);
            *(uint4*)(smem_raw + FQL + so) = *(const uint4*)(qlb + go);
        }
    }

#define LOADKV(t, stg)                                                        \
    {                                                                         \
        uint32_t sp = sbase + FSTG0 + (uint32_t)(stg) * FSTAGE;               \
        const int j0 = (t) * 64;                                              \
        _Pragma("unroll")                                                     \
        for (int u = 0; u < 4; u++) {                                         \
            int seg = tid + u * 256;                                          \
            int row = seg >> 4;                                               \
            int off = (seg & 15) * 16;                                        \
            uint32_t so = (uint32_t)row * FPITCH + off;                       \
            size_t go = ((size_t)(b * SEQ + j0 + row) * DIM + hoff) * 2 + off;\
            cpa16(sp + FKH + so, khb + go);                                   \
            cpa16(sp + FKL + so, klb + go);                                   \
            cpa16(sp + FVH + so, vhb + go);                                   \
            cpa16(sp + FVL + so, vlb + go);                                   \
        }                                                                     \
        CP_COMMIT();                                                          \
    }

    LOADKV(0, 0);

    float o[16][4];
#pragma unroll
    for (int nf = 0; nf < 16; nf++)
#pragma unroll
        for (int k = 0; k < 4; k++) o[nf][k] = 0.0f;
    float m0 = -INFINITY, m1 = -INFINITY, l0s = 0.0f, l1s = 0.0f;

    const uint32_t lmA = (uint32_t)(lane & 15) * FPITCH + (lane >> 4) * 16;
    const uint32_t qAdr = sbase + (uint32_t)(w * 16) * FPITCH + lmA;
    const uint32_t lmV = (uint32_t)(((lane >> 3) & 1) * 8 + (lane & 7)) * FPITCH
                         + (lane >> 4) * 16;

    for (int t = 0; t < 32; t++) {
        const int cur = t & 1;
        CP_WAIT(0);
        __syncthreads();
        if (t + 1 < 32) { LOADKV(t + 1, 1 - cur); }

        const uint32_t stg = sbase + FSTG0 + (uint32_t)cur * FSTAGE;

        float sc[8][4];
#pragma unroll
        for (int nf = 0; nf < 8; nf++)
#pragma unroll
            for (int k = 0; k < 4; k++) sc[nf][k] = 0.0f;

#pragma unroll
        for (int ks = 0; ks < 8; ks++) {
            uint32_t qh[4], ql[4];
            ldsm4(qAdr + FQH + ks * 32, qh[0], qh[1], qh[2], qh[3]);
            ldsm4(qAdr + FQL + ks * 32, ql[0], ql[1], ql[2], ql[3]);
#pragma unroll
            for (int nfp = 0; nfp < 4; nfp++) {
                uint32_t kAdr = stg + (uint32_t)(nfp * 16) * FPITCH + lmA + ks * 32;
                uint32_t kh0, kh1, kh2, kh3, kl0, kl1, kl2, kl3;
                ldsm4(kAdr + FKH, kh0, kh1, kh2, kh3);
                ldsm4(kAdr + FKL, kl0, kl1, kl2, kl3);
                mma_bf16_2(sc[nfp * 2],     qh, kh0, kh2);
                mma_bf16_2(sc[nfp * 2 + 1], qh, kh1, kh3);
                mma_bf16_2(sc[nfp * 2],     qh, kl0, kl2);
                mma_bf16_2(sc[nfp * 2 + 1], qh, kl1, kl3);
                mma_bf16_2(sc[nfp * 2],     ql, kh0, kh2);
                mma_bf16_2(sc[nfp * 2 + 1], ql, kh1, kh3);
            }
        }

        float mx0 = -INFINITY, mx1 = -INFINITY;
#pragma unroll
        for (int nf = 0; nf < 8; nf++) {
            mx0 = fmaxf(mx0, fmaxf(sc[nf][0], sc[nf][1]));
            mx1 = fmaxf(mx1, fmaxf(sc[nf][2], sc[nf][3]));
        }
        mx0 = fmaxf(mx0, __shfl_xor_sync(0xffffffffu, mx0, 1));
        mx0 = fmaxf(mx0, __shfl_xor_sync(0xffffffffu, mx0, 2));
        mx1 = fmaxf(mx1, __shfl_xor_sync(0xffffffffu, mx1, 1));
        mx1 = fmaxf(mx1, __shfl_xor_sync(0xffffffffu, mx1, 2));

        float mn0 = fmaxf(m0, mx0), mn1 = fmaxf(m1, mx1);
        float a0 = __expf(m0 - mn0), a1 = __expf(m1 - mn1);
        float rs0 = 0.0f, rs1 = 0.0f;
#pragma unroll
        for (int nf = 0; nf < 8; nf++) {
            sc[nf][0] = __expf(sc[nf][0] - mn0);
            sc[nf][1] = __expf(sc[nf][1] - mn0);
            sc[nf][2] = __expf(sc[nf][2] - mn1);
            sc[nf][3] = __expf(sc[nf][3] - mn1);
            rs0 += sc[nf][0] + sc[nf][1];
            rs1 += sc[nf][2] + sc[nf][3];
        }
        rs0 += __shfl_xor_sync(0xffffffffu, rs0, 1);
        rs0 += __shfl_xor_sync(0xffffffffu, rs0, 2);
        rs1 += __shfl_xor_sync(0xffffffffu, rs1, 1);
        rs1 += __shfl_xor_sync(0xffffffffu, rs1, 2);
        l0s = l0s * a0 + rs0;
        l1s = l1s * a1 + rs1;
        m0 = mn0; m1 = mn1;
#pragma unroll
        for (int nf = 0; nf < 16; nf++) {
            o[nf][0] *= a0; o[nf][1] *= a0;
            o[nf][2] *= a1; o[nf][3] *= a1;
        }

        uint32_t ph[4][4], pl[4][4];
#pragma unroll
        for (int ks = 0; ks < 4; ks++) {
            split2(sc[2 * ks][0],     sc[2 * ks][1],     ph[ks][0], pl[ks][0]);
            split2(sc[2 * ks][2],     sc[2 * ks][3],     ph[ks][1], pl[ks][1]);
            split2(sc[2 * ks + 1][0], sc[2 * ks + 1][1], ph[ks][2], pl[ks][2]);
            split2(sc[2 * ks + 1][2], sc[2 * ks + 1][3], ph[ks][3], pl[ks][3]);
        }

#pragma unroll
        for (int nfp = 0; nfp < 8; nfp++) {
#pragma unroll
            for (int ks = 0; ks < 4; ks++) {
                uint32_t vAdr = stg + (uint32_t)(ks * 16) * FPITCH + lmV + nfp * 32;
                uint32_t vh0, vh1, vh2, vh3, vl0, vl1, vl2, vl3;
                ldsm4t(vAdr + FVH, vh0, vh1, vh2, vh3);
                ldsm4t(vAdr + FVL, vl0, vl1, vl2, vl3);
                mma_bf16_2(o[nfp * 2],     ph[ks], vh0, vh1);
                mma_bf16_2(o[nfp * 2 + 1], ph[ks], vh2, vh3);
                mma_bf16_2(o[nfp * 2],     ph[ks], vl0, vl1);
                mma_bf16_2(o[nfp * 2 + 1], ph[ks], vl2, vl3);
                mma_bf16_2(o[nfp * 2],     pl[ks], vh0, vh1);
                mma_bf16_2(o[nfp * 2 + 1], pl[ks], vh2, vh3);
            }
        }
        __syncthreads();
    }

    const float inv0 = 1.0f / l0s;
    const float inv1 = 1.0f / l1s;
    const int g = lane >> 2;
    const int tq = lane & 3;
    const int row0 = q0 + w * 16 + g;
    size_t base0 = ((size_t)(b * SEQ + row0)) * DIM + hoff + tq * 2;
    size_t base1 = base0 + (size_t)8 * DIM;
#pragma unroll
    for (int nf = 0; nf < 16; nf++) {
        uint32_t hi, lo;
        split2(o[nf][0] * inv0, o[nf][1] * inv0, hi, lo);
        *(uint32_t*)&g_ah[base0 + nf * 8] = hi;
        *(uint32_t*)&g_al[base0 + nf * 8] = lo;
        split2(o[nf][2] * inv1, o[nf][3] * inv1, hi, lo);
        *(uint32_t*)&g_ah[base1 + nf * 8] = hi;
        *(uint32_t*)&g_al[base1 + nf * 8] = lo;
    }
#undef LOADKV
}

// ---------------------------------------------------------------------------
// Launch
// ---------------------------------------------------------------------------
extern "C" void kernel_launch(void* const* d_in, const int* in_sizes, int n_in,
                              void* d_out, int out_size) {
    const float* x    = (const float*)d_in[0];
    const float* wq   = (const float*)d_in[1];
    const float* wk   = (const float*)d_in[2];
    const float* wv   = (const float*)d_in[3];
    const float* wo   = (const float*)d_in[4];
    const float* fcos = (const float*)d_in[5];
    const float* fsin = (const float*)d_in[6];
    float* out = (float*)d_out;

    __nv_bfloat16 *xh, *xl, *wqh, *wql, *wkh, *wkl, *wvh, *wvl, *woh, *wol;
    __nv_bfloat16 *qh, *ql, *kh, *kl, *vh, *vl, *ah, *al;
    cudaGetSymbolAddress((void**)&xh,  g_xh);
    cudaGetSymbolAddress((void**)&xl,  g_xl);
    cudaGetSymbolAddress((void**)&wqh, g_wqh);
    cudaGetSymbolAddress((void**)&wql, g_wql);
    cudaGetSymbolAddress((void**)&wkh, g_wkh);
    cudaGetSymbolAddress((void**)&wkl, g_wkl);
    cudaGetSymbolAddress((void**)&wvh, g_wvh);
    cudaGetSymbolAddress((void**)&wvl, g_wvl);
    cudaGetSymbolAddress((void**)&woh, g_woh);
    cudaGetSymbolAddress((void**)&wol, g_wol);
    cudaGetSymbolAddress((void**)&qh,  g_qh);
    cudaGetSymbolAddress((void**)&ql,  g_ql);
    cudaGetSymbolAddress((void**)&kh,  g_kh);
    cudaGetSymbolAddress((void**)&kl,  g_kl);
    cudaGetSymbolAddress((void**)&vh,  g_vh);
    cudaGetSymbolAddress((void**)&vl,  g_vl);
    cudaGetSymbolAddress((void**)&ah,  g_ah);
    cudaGetSymbolAddress((void**)&al,  g_al);

    cudaFuncSetAttribute(gemm_qkv, cudaFuncAttributeMaxDynamicSharedMemorySize,
                         GEMM_SMEM);
    cudaFuncSetAttribute(gemm_o, cudaFuncAttributeMaxDynamicSharedMemorySize,
                         GEMM_SMEM);
    cudaFuncSetAttribute(flash_mma, cudaFuncAttributeMaxDynamicSharedMemorySize,
                         FLASH_SMEM);

    split5_kernel<<<dim3(NELEM / 4 / 256, 5), 256>>>(x, wq, wk, wv, wo);

    dim3 ggrid(DIM / BN, MROWS / BM);   // (32, 32)
    gemm_qkv<<<ggrid, GTHREADS, GEMM_SMEM>>>(xh, xl, wqh, wql, qh, ql, fcos, fsin, 0);
    gemm_qkv<<<ggrid, GTHREADS, GEMM_SMEM>>>(xh, xl, wkh, wkl, kh, kl, fcos, fsin, 1);
    gemm_qkv<<<ggrid, GTHREADS, GEMM_SMEM>>>(xh, xl, wvh, wvl, vh, vl, fcos, fsin, 2);

    flash_mma<<<dim3(SEQ / 128, NHEAD, BATCH), 256, FLASH_SMEM>>>();

    gemm_o<<<ggrid, GTHREADS, GEMM_SMEM>>>(ah, al, woh, wol, out);
}

// round 17
// speedup vs baseline: 1.0260x; 1.0004x over previous
#include <cuda_runtime.h>
#include <cuda_bf16.h>
#include <math.h>
#include <stdint.h>

// Problem constants
#define BATCH 2
#define SEQ   2048
#define DIM   4096
#define NHEAD 32
#define HDIM  128
#define MROWS (BATCH * SEQ)   // 4096
#define NELEM (MROWS * DIM)   // 16777216

// pre-split bf16 scratch
__device__ __nv_bfloat16 g_xh[NELEM],  g_xl[NELEM];
__device__ __nv_bfloat16 g_wqh[NELEM], g_wql[NELEM];
__device__ __nv_bfloat16 g_wkh[NELEM], g_wkl[NELEM];
__device__ __nv_bfloat16 g_wvh[NELEM], g_wvl[NELEM];
__device__ __nv_bfloat16 g_woh[NELEM], g_wol[NELEM];
__device__ __nv_bfloat16 g_qh[NELEM],  g_ql[NELEM];
__device__ __nv_bfloat16 g_kh[NELEM],  g_kl[NELEM];
__device__ __nv_bfloat16 g_vh[NELEM],  g_vl[NELEM];
__device__ __nv_bfloat16 g_ah[NELEM],  g_al[NELEM];

// ---------------------------------------------------------------------------
// Helpers
// ---------------------------------------------------------------------------
__device__ __forceinline__ uint32_t smem_u32(const void* p) {
    uint32_t a;
    asm("{ .reg .u64 t; cvta.to.shared.u64 t, %1; cvt.u32.u64 %0, t; }"
        : "=r"(a) : "l"(p));
    return a;
}

__device__ __forceinline__ void cpa16(uint32_t dst, const void* src) {
    asm volatile("cp.async.cg.shared.global [%0], [%1], 16;"
                 :: "r"(dst), "l"(src));
}
#define CP_COMMIT() asm volatile("cp.async.commit_group;" ::: "memory")
#define CP_WAIT(n)  asm volatile("cp.async.wait_group " #n ";" ::: "memory")

__device__ __forceinline__ void ldsm4(uint32_t addr, uint32_t& r0, uint32_t& r1,
                                      uint32_t& r2, uint32_t& r3) {
    asm volatile("ldmatrix.sync.aligned.m8n8.x4.shared.b16 {%0,%1,%2,%3}, [%4];"
                 : "=r"(r0), "=r"(r1), "=r"(r2), "=r"(r3) : "r"(addr));
}
__device__ __forceinline__ void ldsm4t(uint32_t addr, uint32_t& r0, uint32_t& r1,
                                       uint32_t& r2, uint32_t& r3) {
    asm volatile("ldmatrix.sync.aligned.m8n8.x4.trans.shared.b16 {%0,%1,%2,%3}, [%4];"
                 : "=r"(r0), "=r"(r1), "=r"(r2), "=r"(r3) : "r"(addr));
}

__device__ __forceinline__ void mma_bf16(float* c, const uint32_t* a,
                                         const uint32_t* b) {
    asm volatile(
        "mma.sync.aligned.m16n8k16.row.col.f32.bf16.bf16.f32 "
        "{%0,%1,%2,%3}, {%4,%5,%6,%7}, {%8,%9}, {%0,%1,%2,%3};"
        : "+f"(c[0]), "+f"(c[1]), "+f"(c[2]), "+f"(c[3])
        : "r"(a[0]), "r"(a[1]), "r"(a[2]), "r"(a[3]), "r"(b[0]), "r"(b[1]));
}
__device__ __forceinline__ void mma_bf16_2(float* c, const uint32_t* a,
                                           uint32_t b0, uint32_t b1) {
    asm volatile(
        "mma.sync.aligned.m16n8k16.row.col.f32.bf16.bf16.f32 "
        "{%0,%1,%2,%3}, {%4,%5,%6,%7}, {%8,%9}, {%0,%1,%2,%3};"
        : "+f"(c[0]), "+f"(c[1]), "+f"(c[2]), "+f"(c[3])
        : "r"(a[0]), "r"(a[1]), "r"(a[2]), "r"(a[3]), "r"(b0), "r"(b1));
}

__device__ __forceinline__ uint32_t packbf(__nv_bfloat16 a, __nv_bfloat16 b) {
    return ((uint32_t)__bfloat16_as_ushort(b) << 16) | __bfloat16_as_ushort(a);
}
__device__ __forceinline__ void split2(float x, float y, uint32_t& hi, uint32_t& lo) {
    __nv_bfloat16 hx = __float2bfloat16(x);
    __nv_bfloat16 hy = __float2bfloat16(y);
    hi = packbf(hx, hy);
    lo = packbf(__float2bfloat16(x - __bfloat162float(hx)),
                __float2bfloat16(y - __bfloat162float(hy)));
}

// ---------------------------------------------------------------------------
// Merged split kernel
// ---------------------------------------------------------------------------
__global__ __launch_bounds__(256) void split5_kernel(
    const float* __restrict__ s0, const float* __restrict__ s1,
    const float* __restrict__ s2, const float* __restrict__ s3,
    const float* __restrict__ s4) {
    int i = blockIdx.x * blockDim.x + threadIdx.x;
    const float* src;
    __nv_bfloat16 *dh, *dl;
    switch (blockIdx.y) {
        case 0:  src = s0; dh = g_xh;  dl = g_xl;  break;
        case 1:  src = s1; dh = g_wqh; dl = g_wql; break;
        case 2:  src = s2; dh = g_wkh; dl = g_wkl; break;
        case 3:  src = s3; dh = g_wvh; dl = g_wvl; break;
        default: src = s4; dh = g_woh; dl = g_wol; break;
    }
    float4 v = ((const float4*)src)[i];
    uint32_t h0, l0, h1, l1;
    split2(v.x, v.y, h0, l0);
    split2(v.z, v.w, h1, l1);
    ((uint2*)dh)[i] = make_uint2(h0, h1);
    ((uint2*)dl)[i] = make_uint2(l0, l1);
}

// ---------------------------------------------------------------------------
// bf16x3 GEMM core (R11 + ldsm reorder): 128x128 tile, BK=32, 512 threads /
// 16 warps (4x4, warp tile 32x32). 4-stage cp.async pipeline.
// bH loads issued before bL so the hh MMA pass overlaps the bL ldsm latency.
// ---------------------------------------------------------------------------
#define BM 128
#define BN 128
#define BK 32
#define NKC (DIM / BK)   // 128
#define PITCHB 80

#define OFF_AHI 0
#define OFF_ALO 10240
#define OFF_BHI 20480
#define OFF_BLO 30720
#define STAGE_BYTES 40960
#define GEMM_SMEM (4 * STAGE_BYTES)   // 163840
#define GTHREADS 512

#define ISSUE(kc, stg)                                                        \
    {                                                                         \
        uint32_t sb = sbase + (uint32_t)(stg) * STAGE_BYTES;                  \
        size_t gk = (size_t)(kc) * 64;                                        \
        int row = tid >> 2;                                                   \
        int off = (tid & 3) * 16;                                             \
        uint32_t so = (uint32_t)row * PITCHB + off;                           \
        size_t go = (size_t)row * (DIM * 2) + gk + off;                       \
        cpa16(sb + OFF_AHI + so, Ahb + go);                                   \
        cpa16(sb + OFF_ALO + so, Alb + go);                                   \
        cpa16(sb + OFF_BHI + so, Bhb + go);                                   \
        cpa16(sb + OFF_BLO + so, Blb + go);                                   \
        CP_COMMIT();                                                          \
    }

#define GEMM_MAINLOOP(Ahb, Alb, Bhb, Blb)                                     \
    const uint32_t lm_off = (uint32_t)(lane & 15) * PITCHB + (lane >> 4) * 16;\
    const uint32_t aAdr0 = (uint32_t)(wm * 32) * PITCHB + lm_off;             \
    const uint32_t bAdr0 = (uint32_t)(wn * 32) * PITCHB + lm_off;             \
    ISSUE(0, 0); ISSUE(1, 1); ISSUE(2, 2);                                    \
    for (int kc = 0; kc < NKC; kc++) {                                        \
        CP_WAIT(2);                                                           \
        __syncthreads();                                                      \
        if (kc + 3 < NKC) { ISSUE(kc + 3, (kc + 3) & 3); }                    \
        else { CP_COMMIT(); }                                                 \
        const uint32_t stg = sbase + (uint32_t)(kc & 3) * STAGE_BYTES;        \
        const uint32_t aHi = stg + OFF_AHI + aAdr0;                           \
        const uint32_t aLo = stg + OFF_ALO + aAdr0;                           \
        const uint32_t bHi = stg + OFF_BHI + bAdr0;                           \
        const uint32_t bLo = stg + OFF_BLO + bAdr0;                           \
        _Pragma("unroll")                                                     \
        for (int s = 0; s < 2; s++) {                                         \
            uint32_t aF[2][4], bH[4][2], bL[4][2];                            \
            _Pragma("unroll")                                                 \
            for (int mi = 0; mi < 2; mi++)                                    \
                ldsm4(aHi + mi * (16 * PITCHB) + s * 32,                      \
                      aF[mi][0], aF[mi][1], aF[mi][2], aF[mi][3]);            \
            _Pragma("unroll")                                                 \
            for (int nj = 0; nj < 2; nj++) {                                  \
                uint32_t r0, r1, r2, r3;                                      \
                ldsm4(bHi + nj * (16 * PITCHB) + s * 32, r0, r1, r2, r3);     \
                bH[nj * 2][0] = r0; bH[nj * 2 + 1][0] = r1;                   \
                bH[nj * 2][1] = r2; bH[nj * 2 + 1][1] = r3;                   \
            }                                                                 \
            _Pragma("unroll")                                                 \
            for (int nj = 0; nj < 2; nj++) {                                  \
                uint32_t r0, r1, r2, r3;                                      \
                ldsm4(bLo + nj * (16 * PITCHB) + s * 32, r0, r1, r2, r3);     \
                bL[nj * 2][0] = r0; bL[nj * 2 + 1][0] = r1;                   \
                bL[nj * 2][1] = r2; bL[nj * 2 + 1][1] = r3;                   \
            }                                                                 \
            _Pragma("unroll")                                                 \
            for (int mi = 0; mi < 2; mi++)                                    \
                _Pragma("unroll")                                             \
                for (int nf = 0; nf < 4; nf++)                                \
                    mma_bf16(acc[mi][nf], aF[mi], bH[nf]);                    \
            _Pragma("unroll")                                                 \
            for (int mi = 0; mi < 2; mi++)                                    \
                _Pragma("unroll")                                             \
                for (int nf = 0; nf < 4; nf++)                                \
                    mma_bf16(acc[mi][nf], aF[mi], bL[nf]);                    \
            _Pragma("unroll")                                                 \
            for (int mi = 0; mi < 2; mi++)                                    \
                ldsm4(aLo + mi * (16 * PITCHB) + s * 32,                      \
                      aF[mi][0], aF[mi][1], aF[mi][2], aF[mi][3]);            \
            _Pragma("unroll")                                                 \
            for (int mi = 0; mi < 2; mi++)                                    \
                _Pragma("unroll")                                             \
                for (int nf = 0; nf < 4; nf++)                                \
                    mma_bf16(acc[mi][nf], aF[mi], bH[nf]);                    \
        }                                                                     \
        __syncthreads();                                                      \
    }

// ---------------------------------------------------------------------------
// QKV GEMM (one launch per z). RoPE+scale fused with smem-staged trig.
// ---------------------------------------------------------------------------
#define TRIG_PITCH 66

__global__ __launch_bounds__(GTHREADS, 1)
void gemm_qkv(const __nv_bfloat16* __restrict__ Xh,
              const __nv_bfloat16* __restrict__ Xl,
              const __nv_bfloat16* __restrict__ Wh,
              const __nv_bfloat16* __restrict__ Wl,
              __nv_bfloat16* __restrict__ OH,
              __nv_bfloat16* __restrict__ OL,
              const float* __restrict__ fcos, const float* __restrict__ fsin,
              int z) {
    extern __shared__ char smem_raw[];
    const uint32_t sbase = smem_u32(smem_raw);
    const int tid  = threadIdx.x;
    const int wid  = tid >> 5;
    const int lane = tid & 31;
    const int wm   = wid >> 2;        // 0..3
    const int wn   = wid & 3;         // 0..3
    const int m0   = blockIdx.y * BM;
    const int n0   = blockIdx.x * BN;

    const char* Ahb = (const char*)(Xh + (size_t)m0 * DIM);
    const char* Alb = (const char*)(Xl + (size_t)m0 * DIM);
    const char* Bhb = (const char*)(Wh + (size_t)n0 * DIM);
    const char* Blb = (const char*)(Wl + (size_t)n0 * DIM);

    float acc[2][4][4];
#pragma unroll
    for (int i = 0; i < 2; i++)
#pragma unroll
        for (int j = 0; j < 4; j++)
#pragma unroll
            for (int k = 0; k < 4; k++) acc[i][j][k] = 0.0f;

    GEMM_MAINLOOP(Ahb, Alb, Bhb, Blb)

    // Stage trig table into dead pipeline smem
    float2* trig = (float2*)smem_raw;
    if (z < 2) {
        for (int i = tid; i < 128 * 64; i += GTHREADS) {
            int sl = i >> 6, j = i & 63;
            int s = (m0 + sl) & (SEQ - 1);
            trig[sl * TRIG_PITCH + j] = make_float2(fcos[s * 64 + j],
                                                    fsin[s * 64 + j]);
        }
        __syncthreads();
    }

    const float qscale = 0.08838834764831845f;
#pragma unroll
    for (int mi = 0; mi < 2; mi++) {
#pragma unroll
        for (int nf = 0; nf < 4; nf++) {
            int rl  = wm * 32 + mi * 16 + (lane >> 2);
            int row = m0 + rl;
            int col = n0 + wn * 32 + nf * 8 + (lane & 3) * 2;
            float c0 = acc[mi][nf][0], c1 = acc[mi][nf][1];
            float c2 = acc[mi][nf][2], c3 = acc[mi][nf][3];
            if (z < 2) {
                int j = (wn * 32 + nf * 8) / 2 + (lane & 3);
                float2 tA = trig[rl * TRIG_PITCH + j];
                float2 tB = trig[(rl + 8) * TRIG_PITCH + j];
                float r0 = c0 * tA.x - c1 * tA.y, i0 = c0 * tA.y + c1 * tA.x;
                float r1 = c2 * tB.x - c3 * tB.y, i1 = c2 * tB.y + c3 * tB.x;
                if (z == 0) { r0 *= qscale; i0 *= qscale; r1 *= qscale; i1 *= qscale; }
                c0 = r0; c1 = i0; c2 = r1; c3 = i1;
            }
            uint32_t hi, lo;
            split2(c0, c1, hi, lo);
            *(uint32_t*)&OH[(size_t)row * DIM + col] = hi;
            *(uint32_t*)&OL[(size_t)row * DIM + col] = lo;
            split2(c2, c3, hi, lo);
            *(uint32_t*)&OH[(size_t)(row + 8) * DIM + col] = hi;
            *(uint32_t*)&OL[(size_t)(row + 8) * DIM + col] = lo;
        }
    }
}

// ---------------------------------------------------------------------------
// O-projection GEMM (512 threads)
// ---------------------------------------------------------------------------
__global__ __launch_bounds__(GTHREADS, 1)
void gemm_o(const __nv_bfloat16* __restrict__ Ah,
            const __nv_bfloat16* __restrict__ Al,
            const __nv_bfloat16* __restrict__ Bh,
            const __nv_bfloat16* __restrict__ Bl,
            float* __restrict__ C) {
    extern __shared__ char smem_raw[];
    const uint32_t sbase = smem_u32(smem_raw);
    const int tid  = threadIdx.x;
    const int wid  = tid >> 5;
    const int lane = tid & 31;
    const int wm   = wid >> 2;
    const int wn   = wid & 3;
    const int m0   = blockIdx.y * BM;
    const int n0   = blockIdx.x * BN;

    const char* Ahb = (const char*)(Ah + (size_t)m0 * DIM);
    const char* Alb = (const char*)(Al + (size_t)m0 * DIM);
    const char* Bhb = (const char*)(Bh + (size_t)n0 * DIM);
    const char* Blb = (const char*)(Bl + (size_t)n0 * DIM);

    float acc[2][4][4];
#pragma unroll
    for (int i = 0; i < 2; i++)
#pragma unroll
        for (int j = 0; j < 4; j++)
#pragma unroll
            for (int k = 0; k < 4; k++) acc[i][j][k] = 0.0f;

    GEMM_MAINLOOP(Ahb, Alb, Bhb, Blb)

#pragma unroll
    for (int mi = 0; mi < 2; mi++) {
#pragma unroll
        for (int nf = 0; nf < 4; nf++) {
            int row = m0 + wm * 32 + mi * 16 + (lane >> 2);
            int col = n0 + wn * 32 + nf * 8 + (lane & 3) * 2;
            *(float2*)&C[(size_t)row * DIM + col] =
                make_float2(acc[mi][nf][0], acc[mi][nf][1]);
            *(float2*)&C[(size_t)(row + 8) * DIM + col] =
                make_float2(acc[mi][nf][2], acc[mi][nf][3]);
        }
    }
}

// ---------------------------------------------------------------------------
// Flash attention (R5 exactly — at the half-rate HMMA ceiling; untouched)
// ---------------------------------------------------------------------------
#define FPITCH 272
#define FQH 0
#define FQL (128 * FPITCH)
#define FSTG0 (2 * 128 * FPITCH)
#define FKH 0
#define FKL (64 * FPITCH)
#define FVH (128 * FPITCH)
#define FVL (192 * FPITCH)
#define FSTAGE (256 * FPITCH)
#define FLASH_SMEM (FSTG0 + 2 * FSTAGE)

__global__ __launch_bounds__(256)
void flash_mma() {
    extern __shared__ char smem_raw[];
    const uint32_t sbase = smem_u32(smem_raw);
    const int tid  = threadIdx.x;
    const int w    = tid >> 5;
    const int lane = tid & 31;
    const int qt = blockIdx.x;
    const int h  = blockIdx.y;
    const int b  = blockIdx.z;
    const int q0 = qt * 128;
    const size_t hoff = (size_t)h * HDIM;

    const char* khb = (const char*)g_kh;
    const char* klb = (const char*)g_kl;
    const char* vhb = (const char*)g_vh;
    const char* vlb = (const char*)g_vl;

    {
        const char* qhb = (const char*)g_qh;
        const char* qlb = (const char*)g_ql;
        for (int i = tid; i < 2048; i += 256) {
            int r = i >> 4, sg = (i & 15) * 16;
            size_t go = ((size_t)(b * SEQ + q0 + r) * DIM + hoff) * 2 + sg;
            uint32_t so = (uint32_t)r * FPITCH + sg;
            *(uint4*)(smem_raw + FQH + so) = *(const uint4*)(qhb + go);
            *(uint4*)(smem_raw + FQL + so) = *(const uint4*)(qlb + go);
        }
    }

#define LOADKV(t, stg)                                                        \
    {                                                                         \
        uint32_t sp = sbase + FSTG0 + (uint32_t)(stg) * FSTAGE;               \
        const int j0 = (t) * 64;                                              \
        _Pragma("unroll")                                                     \
        for (int u = 0; u < 4; u++) {                                         \
            int seg = tid + u * 256;                                          \
            int row = seg >> 4;                                               \
            int off = (seg & 15) * 16;                                        \
            uint32_t so = (uint32_t)row * FPITCH + off;                       \
            size_t go = ((size_t)(b * SEQ + j0 + row) * DIM + hoff) * 2 + off;\
            cpa16(sp + FKH + so, khb + go);                                   \
            cpa16(sp + FKL + so, klb + go);                                   \
            cpa16(sp + FVH + so, vhb + go);                                   \
            cpa16(sp + FVL + so, vlb + go);                                   \
        }                                                                     \
        CP_COMMIT();                                                          \
    }

    LOADKV(0, 0);

    float o[16][4];
#pragma unroll
    for (int nf = 0; nf < 16; nf++)
#pragma unroll
        for (int k = 0; k < 4; k++) o[nf][k] = 0.0f;
    float m0 = -INFINITY, m1 = -INFINITY, l0s = 0.0f, l1s = 0.0f;

    const uint32_t lmA = (uint32_t)(lane & 15) * FPITCH + (lane >> 4) * 16;
    const uint32_t qAdr = sbase + (uint32_t)(w * 16) * FPITCH + lmA;
    const uint32_t lmV = (uint32_t)(((lane >> 3) & 1) * 8 + (lane & 7)) * FPITCH
                         + (lane >> 4) * 16;

    for (int t = 0; t < 32; t++) {
        const int cur = t & 1;
        CP_WAIT(0);
        __syncthreads();
        if (t + 1 < 32) { LOADKV(t + 1, 1 - cur); }

        const uint32_t stg = sbase + FSTG0 + (uint32_t)cur * FSTAGE;

        float sc[8][4];
#pragma unroll
        for (int nf = 0; nf < 8; nf++)
#pragma unroll
            for (int k = 0; k < 4; k++) sc[nf][k] = 0.0f;

#pragma unroll
        for (int ks = 0; ks < 8; ks++) {
            uint32_t qh[4], ql[4];
            ldsm4(qAdr + FQH + ks * 32, qh[0], qh[1], qh[2], qh[3]);
            ldsm4(qAdr + FQL + ks * 32, ql[0], ql[1], ql[2], ql[3]);
#pragma unroll
            for (int nfp = 0; nfp < 4; nfp++) {
                uint32_t kAdr = stg + (uint32_t)(nfp * 16) * FPITCH + lmA + ks * 32;
                uint32_t kh0, kh1, kh2, kh3, kl0, kl1, kl2, kl3;
                ldsm4(kAdr + FKH, kh0, kh1, kh2, kh3);
                ldsm4(kAdr + FKL, kl0, kl1, kl2, kl3);
                mma_bf16_2(sc[nfp * 2],     qh, kh0, kh2);
                mma_bf16_2(sc[nfp * 2 + 1], qh, kh1, kh3);
                mma_bf16_2(sc[nfp * 2],     qh, kl0, kl2);
                mma_bf16_2(sc[nfp * 2 + 1], qh, kl1, kl3);
                mma_bf16_2(sc[nfp * 2],     ql, kh0, kh2);
                mma_bf16_2(sc[nfp * 2 + 1], ql, kh1, kh3);
            }
        }

        float mx0 = -INFINITY, mx1 = -INFINITY;
#pragma unroll
        for (int nf = 0; nf < 8; nf++) {
            mx0 = fmaxf(mx0, fmaxf(sc[nf][0], sc[nf][1]));
            mx1 = fmaxf(mx1, fmaxf(sc[nf][2], sc[nf][3]));
        }
        mx0 = fmaxf(mx0, __shfl_xor_sync(0xffffffffu, mx0, 1));
        mx0 = fmaxf(mx0, __shfl_xor_sync(0xffffffffu, mx0, 2));
        mx1 = fmaxf(mx1, __shfl_xor_sync(0xffffffffu, mx1, 1));
        mx1 = fmaxf(mx1, __shfl_xor_sync(0xffffffffu, mx1, 2));

        float mn0 = fmaxf(m0, mx0), mn1 = fmaxf(m1, mx1);
        float a0 = __expf(m0 - mn0), a1 = __expf(m1 - mn1);
        float rs0 = 0.0f, rs1 = 0.0f;
#pragma unroll
        for (int nf = 0; nf < 8; nf++) {
            sc[nf][0] = __expf(sc[nf][0] - mn0);
            sc[nf][1] = __expf(sc[nf][1] - mn0);
            sc[nf][2] = __expf(sc[nf][2] - mn1);
            sc[nf][3] = __expf(sc[nf][3] - mn1);
            rs0 += sc[nf][0] + sc[nf][1];
            rs1 += sc[nf][2] + sc[nf][3];
        }
        rs0 += __shfl_xor_sync(0xffffffffu, rs0, 1);
        rs0 += __shfl_xor_sync(0xffffffffu, rs0, 2);
        rs1 += __shfl_xor_sync(0xffffffffu, rs1, 1);
        rs1 += __shfl_xor_sync(0xffffffffu, rs1, 2);
        l0s = l0s * a0 + rs0;
        l1s = l1s * a1 + rs1;
        m0 = mn0; m1 = mn1;
#pragma unroll
        for (int nf = 0; nf < 16; nf++) {
            o[nf][0] *= a0; o[nf][1] *= a0;
            o[nf][2] *= a1; o[nf][3] *= a1;
        }

        uint32_t ph[4][4], pl[4][4];
#pragma unroll
        for (int ks = 0; ks < 4; ks++) {
            split2(sc[2 * ks][0],     sc[2 * ks][1],     ph[ks][0], pl[ks][0]);
            split2(sc[2 * ks][2],     sc[2 * ks][3],     ph[ks][1], pl[ks][1]);
            split2(sc[2 * ks + 1][0], sc[2 * ks + 1][1], ph[ks][2], pl[ks][2]);
            split2(sc[2 * ks + 1][2], sc[2 * ks + 1][3], ph[ks][3], pl[ks][3]);
        }

#pragma unroll
        for (int nfp = 0; nfp < 8; nfp++) {
#pragma unroll
            for (int ks = 0; ks < 4; ks++) {
                uint32_t vAdr = stg + (uint32_t)(ks * 16) * FPITCH + lmV + nfp * 32;
                uint32_t vh0, vh1, vh2, vh3, vl0, vl1, vl2, vl3;
                ldsm4t(vAdr + FVH, vh0, vh1, vh2, vh3);
                ldsm4t(vAdr + FVL, vl0, vl1, vl2, vl3);
                mma_bf16_2(o[nfp * 2],     ph[ks], vh0, vh1);
                mma_bf16_2(o[nfp * 2 + 1], ph[ks], vh2, vh3);
                mma_bf16_2(o[nfp * 2],     ph[ks], vl0, vl1);
                mma_bf16_2(o[nfp * 2 + 1], ph[ks], vl2, vl3);
                mma_bf16_2(o[nfp * 2],     pl[ks], vh0, vh1);
                mma_bf16_2(o[nfp * 2 + 1], pl[ks], vh2, vh3);
            }
        }
        __syncthreads();
    }

    const float inv0 = 1.0f / l0s;
    const float inv1 = 1.0f / l1s;
    const int g = lane >> 2;
    const int tq = lane & 3;
    const int row0 = q0 + w * 16 + g;
    size_t base0 = ((size_t)(b * SEQ + row0)) * DIM + hoff + tq * 2;
    size_t base1 = base0 + (size_t)8 * DIM;
#pragma unroll
    for (int nf = 0; nf < 16; nf++) {
        uint32_t hi, lo;
        split2(o[nf][0] * inv0, o[nf][1] * inv0, hi, lo);
        *(uint32_t*)&g_ah[base0 + nf * 8] = hi;
        *(uint32_t*)&g_al[base0 + nf * 8] = lo;
        split2(o[nf][2] * inv1, o[nf][3] * inv1, hi, lo);
        *(uint32_t*)&g_ah[base1 + nf * 8] = hi;
        *(uint32_t*)&g_al[base1 + nf * 8] = lo;
    }
#undef LOADKV
}

// ---------------------------------------------------------------------------
// Launch
// ---------------------------------------------------------------------------
extern "C" void kernel_launch(void* const* d_in, const int* in_sizes, int n_in,
                              void* d_out, int out_size) {
    const float* x    = (const float*)d_in[0];
    const float* wq   = (const float*)d_in[1];
    const float* wk   = (const float*)d_in[2];
    const float* wv   = (const float*)d_in[3];
    const float* wo   = (const float*)d_in[4];
    const float* fcos = (const float*)d_in[5];
    const float* fsin = (const float*)d_in[6];
    float* out = (float*)d_out;

    __nv_bfloat16 *xh, *xl, *wqh, *wql, *wkh, *wkl, *wvh, *wvl, *woh, *wol;
    __nv_bfloat16 *qh, *ql, *kh, *kl, *vh, *vl, *ah, *al;
    cudaGetSymbolAddress((void**)&xh,  g_xh);
    cudaGetSymbolAddress((void**)&xl,  g_xl);
    cudaGetSymbolAddress((void**)&wqh, g_wqh);
    cudaGetSymbolAddress((void**)&wql, g_wql);
    cudaGetSymbolAddress((void**)&wkh, g_wkh);
    cudaGetSymbolAddress((void**)&wkl, g_wkl);
    cudaGetSymbolAddress((void**)&wvh, g_wvh);
    cudaGetSymbolAddress((void**)&wvl, g_wvl);
    cudaGetSymbolAddress((void**)&woh, g_woh);
    cudaGetSymbolAddress((void**)&wol, g_wol);
    cudaGetSymbolAddress((void**)&qh,  g_qh);
    cudaGetSymbolAddress((void**)&ql,  g_ql);
    cudaGetSymbolAddress((void**)&kh,  g_kh);
    cudaGetSymbolAddress((void**)&kl,  g_kl);
    cudaGetSymbolAddress((void**)&vh,  g_vh);
    cudaGetSymbolAddress((void**)&vl,  g_vl);
    cudaGetSymbolAddress((void**)&ah,  g_ah);
    cudaGetSymbolAddress((void**)&al,  g_al);

    cudaFuncSetAttribute(gemm_qkv, cudaFuncAttributeMaxDynamicSharedMemorySize,
                         GEMM_SMEM);
    cudaFuncSetAttribute(gemm_o, cudaFuncAttributeMaxDynamicSharedMemorySize,
                         GEMM_SMEM);
    cudaFuncSetAttribute(flash_mma, cudaFuncAttributeMaxDynamicSharedMemorySize,
                         FLASH_SMEM);

    split5_kernel<<<dim3(NELEM / 4 / 256, 5), 256>>>(x, wq, wk, wv, wo);

    dim3 ggrid(DIM / BN, MROWS / BM);   // (32, 32)
    gemm_qkv<<<ggrid, GTHREADS, GEMM_SMEM>>>(xh, xl, wqh, wql, qh, ql, fcos, fsin, 0);
    gemm_qkv<<<ggrid, GTHREADS, GEMM_SMEM>>>(xh, xl, wkh, wkl, kh, kl, fcos, fsin, 1);
    gemm_qkv<<<ggrid, GTHREADS, GEMM_SMEM>>>(xh, xl, wvh, wvl, vh, vl, fcos, fsin, 2);

    flash_mma<<<dim3(SEQ / 128, NHEAD, BATCH), 256, FLASH_SMEM>>>();

    gemm_o<<<ggrid, GTHREADS, GEMM_SMEM>>>(ah, al, woh, wol, out);
}